// round 17
// baseline (speedup 1.0000x reference)
#include <cuda_runtime.h>

// LearnedClassVectors: HU bucketize (10 bins) -> 12-dim embedding gather ->
// 4x4x4 patch unfold -> channel-major output (2, 768, 32, 32, 32) fp32.
//
//   x:       (2,1,128,128,128) fp32   d_in[0]
//   vectors: (10,12)           fp32   d_in[1]
//   out:     (2,768,32,32,32)  fp32   50,331,648 elements
//
// R14 = R11 trunk (scalar LDS gather, warp writes contiguous 512B bursts)
// with ONE functional change: the 48-float register staging is chunked into
// 3 x 16 floats (4 v-values at a time) and the kernel is capped at
// __launch_bounds__(256, 5) -> 48 regs -> 5 CTAs/SM -> 40 warps/SM.
// R3/R11 were occupancy-starved at 64 regs / 32 warps with nothing
// saturated (DRAM 57%, L1 59%, issue 19%): latency-bound.

static __device__ __forceinline__ int hu_bin(float v) {
    // searchsorted(edges, v, side='right') == count of edges <= v
    int b = 0;
    b += (v >= -1000.0f);
    b += (v >=   -75.0f);
    b += (v >=     0.0f);
    b += (v >=    15.0f);
    b += (v >=    25.0f);
    b += (v >=    40.0f);
    b += (v >=    50.0f);
    b += (v >=   200.0f);
    b += (v >=  1000.0f);
    return b;
}

__global__ __launch_bounds__(256, 5)
void lcv_kernel(const float* __restrict__ x,
                const float* __restrict__ vectors,
                float* __restrict__ out) {
    // 10 rows x 12 floats; stride 12 spreads row bases across banks
    __shared__ float s_vec[10 * 12];
    if (threadIdx.x < 120) s_vec[threadIdx.x] = vectors[threadIdx.x];
    __syncthreads();

    unsigned tid = blockIdx.x * blockDim.x + threadIdx.x;   // 0 .. 262143
    // bit layout: [2:0]=tw  [4:3]=gh_lo  [6:5]=ph  [9:7]=gh_hi  [16:10]=d  [17]=b
    int tw    = tid & 7;
    int gh_lo = (tid >> 3) & 3;
    int ph    = (tid >> 5) & 3;
    int gh_hi = (tid >> 7) & 7;
    int d     = (tid >> 10) & 127;
    int b     = (int)(tid >> 17);

    int gh = gh_hi * 4 + gh_lo;
    int h  = gh * 4 + ph;
    int gd = d >> 2, pd = d & 3;

    // ---- 16 consecutive x values (4x LDG.128; warp = 4 x 512B chunks) ----
    const float4* xp = (const float4*)(x +
        ((size_t)((b * 128 + d) * 128 + h) * 128 + (unsigned)tw * 16u));
    float4 xv0 = xp[0];
    float4 xv1 = xp[1];
    float4 xv2 = xp[2];
    float4 xv3 = xp[3];

    // bins[gwi][pw]: voxel (gw = 4*tw + gwi, pw) is xv[gwi] component pw
    int bins[4][4];
    bins[0][0] = hu_bin(xv0.x); bins[0][1] = hu_bin(xv0.y);
    bins[0][2] = hu_bin(xv0.z); bins[0][3] = hu_bin(xv0.w);
    bins[1][0] = hu_bin(xv1.x); bins[1][1] = hu_bin(xv1.y);
    bins[1][2] = hu_bin(xv1.z); bins[1][3] = hu_bin(xv1.w);
    bins[2][0] = hu_bin(xv2.x); bins[2][1] = hu_bin(xv2.y);
    bins[2][2] = hu_bin(xv2.z); bins[2][3] = hu_bin(xv2.w);
    bins[3][0] = hu_bin(xv3.x); bins[3][1] = hu_bin(xv3.y);
    bins[3][2] = hu_bin(xv3.z); bins[3][3] = hu_bin(xv3.w);

    // ---- output addressing: all lanes of a warp share the channel; the
    // warp's 32 float4 stores tile one contiguous 512B block ----
    float* ob = out + (size_t)b * (768u * 32768u)
                    + (unsigned)gd * 1024u + (unsigned)gh * 32u
                    + (unsigned)tw * 4u;
    int chbase = (pd * 16 + ph * 4) * 12;   // + pw*12 + v

#pragma unroll
    for (int pw = 0; pw < 4; pw++) {
        const float* r0 = &s_vec[bins[0][pw] * 12];
        const float* r1 = &s_vec[bins[1][pw] * 12];
        const float* r2 = &s_vec[bins[2][pw] * 12];
        const float* r3 = &s_vec[bins[3][pw] * 12];

        float* op = ob + (size_t)(chbase + pw * 12) * 32768u;

        // 3 chunks of 4 v-values: 16 scalar LDS staged (16 live floats),
        // then 4 STG.128. Chunks pipeline: next chunk's independent LDS
        // issue while this chunk's stores drain.
#pragma unroll
        for (int vc = 0; vc < 3; vc++) {
            float a0[4], a1[4], a2[4], a3[4];
#pragma unroll
            for (int j = 0; j < 4; j++) {
                int v = vc * 4 + j;
                a0[j] = r0[v]; a1[j] = r1[v]; a2[j] = r2[v]; a3[j] = r3[v];
            }
#pragma unroll
            for (int j = 0; j < 4; j++) {
                *(float4*)op = make_float4(a0[j], a1[j], a2[j], a3[j]);
                op += 32768;                 // next channel, same spatial
            }
        }
    }
}

extern "C" void kernel_launch(void* const* d_in, const int* in_sizes, int n_in,
                              void* d_out, int out_size) {
    const float* x       = (const float*)d_in[0];
    const float* vectors = (const float*)d_in[1];
    float* out           = (float*)d_out;

    // 262144 threads, one 16-voxel w-tile each: 1024 blocks
    lcv_kernel<<<1024, 256>>>(x, vectors, out);
}